// round 10
// baseline (speedup 1.0000x reference)
#include <cuda_runtime.h>
#include <cstdint>

// ---------------------------------------------------------------------------
// GCN 2-layer forward on GB300 — round 10: fp32 H restored; gather1 load-chain
// broken via interleaved edge metadata (float2) + software-pipelined prefetch.
//   h  = x @ W1                 (mma.sync tf32, 50000x512 @ 512x256)
//   a1 = Dinv (A+I) Dinv h ; +b1 ; ELU ; dropout(p=0.25, jax threefry)
//   p  = a1 @ W2                (fused: group dot-product in gather1)
//   out= Dinv (A+I) Dinv p + b2
// ---------------------------------------------------------------------------

#define NMAX 50048
#define EMAX 1000000
#define CIN  512
#define CH   256

// GEMM1 tiling
#define CTA_M 128
#define CTA_N 128
#define CTA_K 32
#define NSTG  (CIN / CTA_K)          // 16
#define APAD  36
#define BPAD  136
#define SM_A_BYTES (CTA_M * APAD * 4)
#define SM_B_BYTES (CTA_K * BPAD * 4)
#define SM_STAGE   (SM_A_BYTES + SM_B_BYTES)
#define SM_TOTAL   (2 * SM_STAGE)

__device__ int    g_DEGI[NMAX];
__device__ float  g_DINV[NMAX];
__device__ int    g_ROWPTR[NMAX + 1];
__device__ int    g_CUR[NMAX];
__device__ float2 g_EDG[EMAX];       // .x = __int_as_float(src), .y = norm
__device__ float  g_H  [(size_t)NMAX * CH];
__device__ float  g_P  [NMAX];
__device__ float  g_W1R[(size_t)CIN * CH];
__device__ int    g_is64;

__device__ __forceinline__ float to_tf32(float x) {
    float r;
    asm("cvt.rna.tf32.f32 %0, %1;" : "=f"(r) : "f"(x));
    return r;
}
__device__ __forceinline__ uint32_t smem_u32(const void* p) {
    uint32_t a;
    asm("{ .reg .u64 t; cvta.to.shared.u64 t, %1; cvt.u32.u64 %0, t; }"
        : "=r"(a) : "l"(p));
    return a;
}
__device__ __forceinline__ void cp_async16(uint32_t dst, const void* src) {
    asm volatile("cp.async.ca.shared.global [%0], [%1], 16;"
                 :: "r"(dst), "l"(src));
}
#define CP_COMMIT() asm volatile("cp.async.commit_group;" ::: "memory")
#define CP_WAIT(n)  asm volatile("cp.async.wait_group %0;" :: "n"(n) : "memory")

__device__ __forceinline__ void mma_tf32(float* c, const float* a, const float* b) {
    asm volatile(
        "mma.sync.aligned.m16n8k8.row.col.f32.tf32.tf32.f32 "
        "{%0,%1,%2,%3}, {%4,%5,%6,%7}, {%8,%9}, {%0,%1,%2,%3};"
        : "+f"(c[0]), "+f"(c[1]), "+f"(c[2]), "+f"(c[3])
        : "r"(__float_as_uint(a[0])), "r"(__float_as_uint(a[1])),
          "r"(__float_as_uint(a[2])), "r"(__float_as_uint(a[3])),
          "r"(__float_as_uint(b[0])), "r"(__float_as_uint(b[1])));
}

// ---------------------------------------------------------------------------
__global__ void detect_kernel(const unsigned* __restrict__ words, int E) {
    if (threadIdx.x == 0 && blockIdx.x == 0) {
        int n = E < 256 ? E : 256;
        unsigned acc = 0u;
        for (int i = 0; i < n; i++) acc |= words[2 * i + 1];
        g_is64 = (acc == 0u) ? 1 : 0;
    }
}
__device__ __forceinline__ int edge_at(const void* ei, int is64, long long idx) {
    if (is64) return (int)((const long long*)ei)[idx];
    return ((const int*)ei)[idx];
}

// ---------------------------------------------------------------------------
__global__ void deg_zero_kernel(int M) {
    int v = blockIdx.x * blockDim.x + threadIdx.x;
    if (v < M) g_DEGI[v] = 0;
}
__global__ void deg_acc_kernel(const void* __restrict__ ei, int E) {
    int e = blockIdx.x * blockDim.x + threadIdx.x;
    if (e >= E) return;
    int d = edge_at(ei, g_is64, (long long)E + e);
    atomicAdd(&g_DEGI[d], 1);
}
// scan + dinv fused: exclusive scan of degrees -> ROWPTR/CUR, plus DINV.
__global__ __launch_bounds__(1024) void scan_kernel(int M) {
    const int T = 1024;
    int tid = threadIdx.x;
    int chunk = (M + T - 1) / T;
    int start = tid * chunk;
    int end   = start + chunk; if (end > M) end = M; if (start > M) start = M;
    int s = 0;
    for (int i = start; i < end; i++) {
        int d = g_DEGI[i];
        s += d;
        g_DINV[i] = rsqrtf((float)(d + 1));
    }
    int lane = tid & 31, wid = tid >> 5;
    int v = s;
    #pragma unroll
    for (int o = 1; o < 32; o <<= 1) {
        int t = __shfl_up_sync(0xffffffffu, v, o);
        if (lane >= o) v += t;
    }
    __shared__ int wsum[32];
    if (lane == 31) wsum[wid] = v;
    __syncthreads();
    if (wid == 0) {
        int w = wsum[lane];
        #pragma unroll
        for (int o = 1; o < 32; o <<= 1) {
            int t = __shfl_up_sync(0xffffffffu, w, o);
            if (lane >= o) w += t;
        }
        wsum[lane] = w;
    }
    __syncthreads();
    int excl = v - s + (wid > 0 ? wsum[wid - 1] : 0);
    int offset = excl;
    for (int i = start; i < end; i++) {
        int d = g_DEGI[i];
        g_ROWPTR[i] = offset;
        g_CUR[i]    = offset;
        offset += d;
    }
    if (tid == T - 1) g_ROWPTR[M] = offset;
}
__global__ void fill_kernel(const void* __restrict__ ei, int E) {
    int e = blockIdx.x * blockDim.x + threadIdx.x;
    if (e >= E) return;
    int is64 = g_is64;
    int s = edge_at(ei, is64, e);
    int d = edge_at(ei, is64, (long long)E + e);
    int pos = atomicAdd(&g_CUR[d], 1);
    g_EDG[pos] = make_float2(__int_as_float(s), g_DINV[s] * g_DINV[d]);
}

// ---------------------------------------------------------------------------
__global__ void w1r_kernel(const float* __restrict__ W1) {
    int idx = blockIdx.x * blockDim.x + threadIdx.x;
    if (idx < CIN * CH) g_W1R[idx] = to_tf32(W1[idx]);
}

// ---------------------------------------------------------------------------
// GEMM1: g_H = X @ W1 via mma.sync.m16n8k8 tf32 (fp32 output, as in R8).
// ---------------------------------------------------------------------------
__global__ __launch_bounds__(256, 2) void gemm1_mma_kernel(
    const float* __restrict__ X, int M)
{
    extern __shared__ float sm[];
    uint32_t smb = smem_u32(sm);

    int tid  = threadIdx.x;
    int wid  = tid >> 5;
    int lane = tid & 31;
    int gid  = lane >> 2;
    int tig  = lane & 3;
    int wm   = wid >> 1;
    int wn   = wid & 1;

    int m0 = blockIdx.x * CTA_M;
    int n0 = blockIdx.y * CTA_N;

    float acc[2][8][4];
    #pragma unroll
    for (int i = 0; i < 2; i++)
        #pragma unroll
        for (int j = 0; j < 8; j++)
            #pragma unroll
            for (int k = 0; k < 4; k++) acc[i][j][k] = 0.0f;

    auto issue = [&](int s, int buf) {
        uint32_t baseA = smb + buf * SM_STAGE;
        uint32_t baseB = baseA + SM_A_BYTES;
        #pragma unroll
        for (int it = 0; it < 4; it++) {
            int id  = it * 256 + tid;
            int ar = id >> 3, akq = id & 7;
            int grow = m0 + ar; if (grow > M - 1) grow = M - 1;
            cp_async16(baseA + (uint32_t)(ar * APAD + akq * 4) * 4,
                       X + (size_t)grow * CIN + s * CTA_K + akq * 4);
            int bk = id >> 5, bnc = id & 31;
            cp_async16(baseB + (uint32_t)(bk * BPAD + bnc * 4) * 4,
                       g_W1R + (size_t)(s * CTA_K + bk) * CH + n0 + bnc * 4);
        }
    };

    issue(0, 0);
    CP_COMMIT();

    for (int s = 0; s < NSTG; s++) {
        int buf = s & 1;
        if (s + 1 < NSTG) {
            issue(s + 1, buf ^ 1);
            CP_COMMIT();
            CP_WAIT(1);
        } else {
            CP_WAIT(0);
        }
        __syncthreads();

        const float* sA = sm + buf * (SM_STAGE / 4);
        const float* sB = sA + (SM_A_BYTES / 4);

        #pragma unroll
        for (int ks = 0; ks < 4; ks++) {
            float a[2][4];
            #pragma unroll
            for (int mt = 0; mt < 2; mt++) {
                int r = wm * 32 + mt * 16 + gid;
                int c = ks * 8 + tig;
                a[mt][0] = to_tf32(sA[r * APAD + c]);
                a[mt][1] = to_tf32(sA[(r + 8) * APAD + c]);
                a[mt][2] = to_tf32(sA[r * APAD + c + 4]);
                a[mt][3] = to_tf32(sA[(r + 8) * APAD + c + 4]);
            }
            float b[8][2];
            #pragma unroll
            for (int nt = 0; nt < 8; nt++) {
                int kk = ks * 8 + tig;
                int cc = wn * 64 + nt * 8 + gid;
                b[nt][0] = sB[kk * BPAD + cc];
                b[nt][1] = sB[(kk + 4) * BPAD + cc];
            }
            #pragma unroll
            for (int mt = 0; mt < 2; mt++)
                #pragma unroll
                for (int nt = 0; nt < 8; nt++)
                    mma_tf32(acc[mt][nt], a[mt], b[nt]);
        }
        __syncthreads();
    }

    #pragma unroll
    for (int mt = 0; mt < 2; mt++) {
        int r0 = m0 + wm * 32 + mt * 16 + gid;
        #pragma unroll
        for (int nt = 0; nt < 8; nt++) {
            int c = n0 + wn * 64 + nt * 8 + 2 * tig;
            if (r0 < M)
                *(float2*)(g_H + (size_t)r0 * CH + c) =
                    make_float2(acc[mt][nt][0], acc[mt][nt][1]);
            if (r0 + 8 < M)
                *(float2*)(g_H + (size_t)(r0 + 8) * CH + c) =
                    make_float2(acc[mt][nt][2], acc[mt][nt][3]);
        }
    }
}

// ---------------------------------------------------------------------------
// threefry2x32, key = (0, 42), partitionable mode: bits = o0 ^ o1
// ---------------------------------------------------------------------------
__device__ __forceinline__ void threefry2x32(unsigned c0, unsigned c1,
                                             unsigned& o0, unsigned& o1) {
    const unsigned ks0 = 0u, ks1 = 42u;
    const unsigned ks2 = 0x1BD11BDAu ^ ks0 ^ ks1;
    unsigned x0 = c0 + ks0;
    unsigned x1 = c1 + ks1;
#define TF_ROUND(r) { x0 += x1; x1 = (x1 << (r)) | (x1 >> (32 - (r))); x1 ^= x0; }
    TF_ROUND(13) TF_ROUND(15) TF_ROUND(26) TF_ROUND(6)
    x0 += ks1; x1 += ks2 + 1u;
    TF_ROUND(17) TF_ROUND(29) TF_ROUND(16) TF_ROUND(24)
    x0 += ks2; x1 += ks0 + 2u;
    TF_ROUND(13) TF_ROUND(15) TF_ROUND(26) TF_ROUND(6)
    x0 += ks0; x1 += ks1 + 3u;
    TF_ROUND(17) TF_ROUND(29) TF_ROUND(16) TF_ROUND(24)
    x0 += ks1; x1 += ks2 + 4u;
    TF_ROUND(13) TF_ROUND(15) TF_ROUND(26) TF_ROUND(6)
    x0 += ks2; x1 += ks0 + 5u;
#undef TF_ROUND
    o0 = x0; o1 = x1;
}

__device__ __forceinline__ float dropout_elu(float acc, float bias, unsigned idx) {
    unsigned o0, o1;
    threefry2x32(0u, idx, o0, o1);
    unsigned bits = o0 ^ o1;
    float u = __uint_as_float((bits >> 9) | 0x3F800000u) - 1.0f;
    float val = acc + bias;
    val = val > 0.0f ? val : expm1f(val);
    return (u < 0.75f) ? val * (1.0f / 0.75f) : 0.0f;
}

// ---------------------------------------------------------------------------
// Layer-1 aggregate + epilogue + fused GEMM2.
// 4 nodes per 256-thread block; 64 threads per node; float4 per thread.
// Edge metadata interleaved (float2) and prefetched one iteration ahead so the
// meta->address->row chain of iteration i+1 overlaps iteration i's row loads.
// ---------------------------------------------------------------------------
__global__ __launch_bounds__(256) void gather1_kernel(
    const float* __restrict__ b1, const float* __restrict__ W2, int M)
{
    int grp = threadIdx.x >> 6;
    int t   = threadIdx.x & 63;
    int v   = blockIdx.x * 4 + grp;
    bool active = (v < M);
    int vv = active ? v : 0;

    const float4* __restrict__ H4 = (const float4*)g_H;
    const float2* __restrict__ EDG = (const float2*)g_EDG;

    float dv = g_DINV[vv];
    float4 h = H4[(size_t)vv * 64 + t];
    float sl = dv * dv;
    float4 acc = make_float4(sl * h.x, sl * h.y, sl * h.z, sl * h.w);

    int beg = active ? g_ROWPTR[vv]     : 0;
    int end = active ? g_ROWPTR[vv + 1] : 0;
    int cnt = end - beg;
    int n4  = cnt & ~3;

    float2 e0, e1, e2, e3;
    if (n4 > 0) {
        e0 = EDG[beg];     e1 = EDG[beg + 1];
        e2 = EDG[beg + 2]; e3 = EDG[beg + 3];
    }
    for (int j = 0; j < n4; j += 4) {
        int   s0 = __float_as_int(e0.x), s1 = __float_as_int(e1.x);
        int   s2 = __float_as_int(e2.x), s3 = __float_as_int(e3.x);
        float n0 = e0.y, n1 = e1.y, n2 = e2.y, n3 = e3.y;

        float4 r0 = H4[(size_t)s0 * 64 + t];
        float4 r1 = H4[(size_t)s1 * 64 + t];
        float4 r2 = H4[(size_t)s2 * 64 + t];
        float4 r3 = H4[(size_t)s3 * 64 + t];

        // prefetch next 4 edges' metadata while row loads are in flight
        if (j + 4 < n4) {
            int p = beg + j + 4;
            e0 = EDG[p];     e1 = EDG[p + 1];
            e2 = EDG[p + 2]; e3 = EDG[p + 3];
        }

        acc.x += n0 * r0.x + n1 * r1.x + n2 * r2.x + n3 * r3.x;
        acc.y += n0 * r0.y + n1 * r1.y + n2 * r2.y + n3 * r3.y;
        acc.z += n0 * r0.z + n1 * r1.z + n2 * r2.z + n3 * r3.z;
        acc.w += n0 * r0.w + n1 * r1.w + n2 * r2.w + n3 * r3.w;
    }
    for (int j = beg + n4; j < end; j++) {
        float2 e = EDG[j];
        int   s0 = __float_as_int(e.x);
        float n0 = e.y;
        float4 r0 = H4[(size_t)s0 * 64 + t];
        acc.x += n0 * r0.x;
        acc.y += n0 * r0.y;
        acc.z += n0 * r0.z;
        acc.w += n0 * r0.w;
    }

    float4 bb = ((const float4*)b1)[t];
    unsigned base = (unsigned)vv * CH + (unsigned)t * 4;
    float a0 = dropout_elu(acc.x, bb.x, base + 0);
    float a1 = dropout_elu(acc.y, bb.y, base + 1);
    float a2 = dropout_elu(acc.z, bb.z, base + 2);
    float a3 = dropout_elu(acc.w, bb.w, base + 3);

    float4 w = ((const float4*)W2)[t];
    float dot = a0 * w.x + a1 * w.y + a2 * w.z + a3 * w.w;
    #pragma unroll
    for (int o = 16; o > 0; o >>= 1)
        dot += __shfl_xor_sync(0xffffffffu, dot, o);

    __shared__ float red[8];
    int lane = t & 31, hw = t >> 5;
    if (lane == 0) red[grp * 2 + hw] = dot;
    __syncthreads();
    if (t == 0 && active) g_P[v] = red[grp * 2] + red[grp * 2 + 1];
}

// ---------------------------------------------------------------------------
// Layer-2 aggregate (CSR gather, scalar). One warp per node.
// ---------------------------------------------------------------------------
__global__ void gather2_kernel(const float* __restrict__ b2,
                               float* __restrict__ out, int M) {
    int gt   = blockIdx.x * blockDim.x + threadIdx.x;
    int warp = gt >> 5;
    int lane = gt & 31;
    if (warp >= M) return;
    int beg = g_ROWPTR[warp];
    int end = g_ROWPTR[warp + 1];
    float s = 0.0f;
    for (int e = beg + lane; e < end; e += 32) {
        float2 m = g_EDG[e];
        s += m.y * g_P[__float_as_int(m.x)];
    }
    #pragma unroll
    for (int o = 16; o > 0; o >>= 1) s += __shfl_xor_sync(0xffffffffu, s, o);
    if (lane == 0) {
        float dv = g_DINV[warp];
        out[warp] = dv * dv * g_P[warp] + b2[0] + s;
    }
}

// ---------------------------------------------------------------------------
extern "C" void kernel_launch(void* const* d_in, const int* in_sizes, int n_in,
                              void* d_out, int out_size) {
    const float* x  = (const float*)d_in[0];
    const void*  ei = d_in[1];
    const float* W1 = (const float*)d_in[2];
    const float* b1 = (const float*)d_in[3];
    const float* W2 = (const float*)d_in[4];
    const float* b2 = (const float*)d_in[5];
    float* out = (float*)d_out;

    int M = in_sizes[0] / CIN;     // 50000
    int E = in_sizes[1] / 2;       // 800000

    static cudaStream_t s2 = nullptr;
    static cudaEvent_t evFork = nullptr, evJoin = nullptr;
    if (!s2) {
        cudaFuncSetAttribute(gemm1_mma_kernel,
                             cudaFuncAttributeMaxDynamicSharedMemorySize, SM_TOTAL);
        cudaStreamCreateWithFlags(&s2, cudaStreamNonBlocking);
        cudaEventCreateWithFlags(&evFork, cudaEventDisableTiming);
        cudaEventCreateWithFlags(&evJoin, cudaEventDisableTiming);
    }

    // ---- fork: CSR build on s2, GEMM1 on stream 0 ----
    cudaEventRecord(evFork, 0);
    cudaStreamWaitEvent(s2, evFork, 0);

    detect_kernel  <<<1, 32, 0, s2>>>((const unsigned*)ei, E);
    deg_zero_kernel<<<(M + 255) / 256, 256, 0, s2>>>(M);
    deg_acc_kernel <<<(E + 255) / 256, 256, 0, s2>>>(ei, E);
    scan_kernel    <<<1, 1024, 0, s2>>>(M);                 // scan + dinv fused
    fill_kernel    <<<(E + 255) / 256, 256, 0, s2>>>(ei, E);

    w1r_kernel<<<(CIN * CH + 255) / 256, 256>>>(W1);
    dim3 g1((M + CTA_M - 1) / CTA_M, CH / CTA_N);  // (391, 2)
    gemm1_mma_kernel<<<g1, 256, SM_TOTAL>>>(x, M);

    cudaEventRecord(evJoin, s2);
    cudaStreamWaitEvent(0, evJoin, 0);

    gather1_kernel<<<(M + 3) / 4, 256>>>(b1, W2, M);
    gather2_kernel<<<(M * 32 + 255) / 256, 256>>>(b2, out, M);
}

// round 11
// speedup vs baseline: 1.6804x; 1.6804x over previous
#include <cuda_runtime.h>
#include <cstdint>

// ---------------------------------------------------------------------------
// GCN 2-layer forward on GB300 — round 11: R8 baseline + 3-phase parallel scan
// (the single-block scan was 103us on the critical path, caught by ncu).
//   h  = x @ W1                 (mma.sync tf32, 50000x512 @ 512x256)
//   a1 = Dinv (A+I) Dinv h ; +b1 ; ELU ; dropout(p=0.25, jax threefry)
//   p  = a1 @ W2                (fused: group dot-product in gather1)
//   out= Dinv (A+I) Dinv p + b2
// ---------------------------------------------------------------------------

#define NMAX 50048
#define EMAX 1000000
#define CIN  512
#define CH   256
#define SCAN_NB ((NMAX + 255) / 256)   // 196 tiles

// GEMM1 tiling
#define CTA_M 128
#define CTA_N 128
#define CTA_K 32
#define NSTG  (CIN / CTA_K)          // 16
#define APAD  36
#define BPAD  136
#define SM_A_BYTES (CTA_M * APAD * 4)
#define SM_B_BYTES (CTA_K * BPAD * 4)
#define SM_STAGE   (SM_A_BYTES + SM_B_BYTES)
#define SM_TOTAL   (2 * SM_STAGE)

__device__ int    g_DEGI[NMAX];
__device__ float  g_DINV[NMAX];
__device__ int    g_ROWPTR[NMAX + 1];
__device__ int    g_CUR[NMAX];
__device__ int    g_PART[SCAN_NB];
__device__ int    g_SRC[EMAX];
__device__ float  g_NRM[EMAX];
__device__ float  g_H  [(size_t)NMAX * CH];
__device__ float  g_P  [NMAX];
__device__ float  g_W1R[(size_t)CIN * CH];
__device__ int    g_is64;

__device__ __forceinline__ float to_tf32(float x) {
    float r;
    asm("cvt.rna.tf32.f32 %0, %1;" : "=f"(r) : "f"(x));
    return r;
}
__device__ __forceinline__ uint32_t smem_u32(const void* p) {
    uint32_t a;
    asm("{ .reg .u64 t; cvta.to.shared.u64 t, %1; cvt.u32.u64 %0, t; }"
        : "=r"(a) : "l"(p));
    return a;
}
__device__ __forceinline__ void cp_async16(uint32_t dst, const void* src) {
    asm volatile("cp.async.ca.shared.global [%0], [%1], 16;"
                 :: "r"(dst), "l"(src));
}
#define CP_COMMIT() asm volatile("cp.async.commit_group;" ::: "memory")
#define CP_WAIT(n)  asm volatile("cp.async.wait_group %0;" :: "n"(n) : "memory")

__device__ __forceinline__ void mma_tf32(float* c, const float* a, const float* b) {
    asm volatile(
        "mma.sync.aligned.m16n8k8.row.col.f32.tf32.tf32.f32 "
        "{%0,%1,%2,%3}, {%4,%5,%6,%7}, {%8,%9}, {%0,%1,%2,%3};"
        : "+f"(c[0]), "+f"(c[1]), "+f"(c[2]), "+f"(c[3])
        : "r"(__float_as_uint(a[0])), "r"(__float_as_uint(a[1])),
          "r"(__float_as_uint(a[2])), "r"(__float_as_uint(a[3])),
          "r"(__float_as_uint(b[0])), "r"(__float_as_uint(b[1])));
}

// ---------------------------------------------------------------------------
__global__ void detect_kernel(const unsigned* __restrict__ words, int E) {
    if (threadIdx.x == 0 && blockIdx.x == 0) {
        int n = E < 256 ? E : 256;
        unsigned acc = 0u;
        for (int i = 0; i < n; i++) acc |= words[2 * i + 1];
        g_is64 = (acc == 0u) ? 1 : 0;
    }
}
__device__ __forceinline__ int edge_at(const void* ei, int is64, long long idx) {
    if (is64) return (int)((const long long*)ei)[idx];
    return ((const int*)ei)[idx];
}

// ---------------------------------------------------------------------------
__global__ void deg_zero_kernel(int M) {
    int v = blockIdx.x * blockDim.x + threadIdx.x;
    if (v < M) g_DEGI[v] = 0;
}
__global__ void deg_acc_kernel(const void* __restrict__ ei, int E) {
    int e = blockIdx.x * blockDim.x + threadIdx.x;
    if (e >= E) return;
    int d = edge_at(ei, g_is64, (long long)E + e);
    atomicAdd(&g_DEGI[d], 1);
}
__global__ void dinv_kernel(int M) {
    int v = blockIdx.x * blockDim.x + threadIdx.x;
    if (v < M) g_DINV[v] = rsqrtf((float)(g_DEGI[v] + 1));
}

// ---------------------------------------------------------------------------
// 3-phase parallel exclusive scan of DEGI -> ROWPTR, CUR
// ---------------------------------------------------------------------------
// block-wide inclusive scan helper (256 threads)
__device__ __forceinline__ int block_incl_scan(int val, int* smem32) {
    int lane = threadIdx.x & 31, wid = threadIdx.x >> 5;
    int v = val;
    #pragma unroll
    for (int o = 1; o < 32; o <<= 1) {
        int t = __shfl_up_sync(0xffffffffu, v, o);
        if (lane >= o) v += t;
    }
    if (lane == 31) smem32[wid] = v;
    __syncthreads();
    if (wid == 0) {
        int w = (lane < 8) ? smem32[lane] : 0;
        #pragma unroll
        for (int o = 1; o < 8; o <<= 1) {
            int t = __shfl_up_sync(0xffffffffu, w, o);
            if (lane >= o) w += t;
        }
        if (lane < 8) smem32[lane] = w;
    }
    __syncthreads();
    return v + (wid > 0 ? smem32[wid - 1] : 0);
}

__global__ __launch_bounds__(256) void scan1_kernel(int M) {
    __shared__ int sm32[32];
    int i = blockIdx.x * 256 + threadIdx.x;
    int d = (i < M) ? g_DEGI[i] : 0;
    int incl = block_incl_scan(d, sm32);
    if (threadIdx.x == 255) g_PART[blockIdx.x] = incl;
}

__global__ __launch_bounds__(256) void scan2_kernel(int nb) {
    __shared__ int sm32[32];
    int tid = threadIdx.x;
    int v = (tid < nb) ? g_PART[tid] : 0;
    int incl = block_incl_scan(v, sm32);
    if (tid < nb) g_PART[tid] = incl - v;   // exclusive
}

__global__ __launch_bounds__(256) void scan3_kernel(int M) {
    __shared__ int sm32[32];
    int i = blockIdx.x * 256 + threadIdx.x;
    int d = (i < M) ? g_DEGI[i] : 0;
    int incl = block_incl_scan(d, sm32);
    int off = g_PART[blockIdx.x] + incl - d;
    if (i < M) {
        g_ROWPTR[i] = off;
        g_CUR[i]    = off;
        if (i == M - 1) g_ROWPTR[M] = off + d;
    }
}

__global__ void fill_kernel(const void* __restrict__ ei, int E) {
    int e = blockIdx.x * blockDim.x + threadIdx.x;
    if (e >= E) return;
    int is64 = g_is64;
    int s = edge_at(ei, is64, e);
    int d = edge_at(ei, is64, (long long)E + e);
    int pos = atomicAdd(&g_CUR[d], 1);
    g_SRC[pos] = s;
    g_NRM[pos] = g_DINV[s] * g_DINV[d];
}

// ---------------------------------------------------------------------------
__global__ void w1r_kernel(const float* __restrict__ W1) {
    int idx = blockIdx.x * blockDim.x + threadIdx.x;
    if (idx < CIN * CH) g_W1R[idx] = to_tf32(W1[idx]);
}

// ---------------------------------------------------------------------------
// GEMM1: g_H = X @ W1 via mma.sync.m16n8k8 tf32 (unchanged from R8).
// ---------------------------------------------------------------------------
__global__ __launch_bounds__(256, 2) void gemm1_mma_kernel(
    const float* __restrict__ X, int M)
{
    extern __shared__ float sm[];
    uint32_t smb = smem_u32(sm);

    int tid  = threadIdx.x;
    int wid  = tid >> 5;
    int lane = tid & 31;
    int gid  = lane >> 2;
    int tig  = lane & 3;
    int wm   = wid >> 1;
    int wn   = wid & 1;

    int m0 = blockIdx.x * CTA_M;
    int n0 = blockIdx.y * CTA_N;

    float acc[2][8][4];
    #pragma unroll
    for (int i = 0; i < 2; i++)
        #pragma unroll
        for (int j = 0; j < 8; j++)
            #pragma unroll
            for (int k = 0; k < 4; k++) acc[i][j][k] = 0.0f;

    auto issue = [&](int s, int buf) {
        uint32_t baseA = smb + buf * SM_STAGE;
        uint32_t baseB = baseA + SM_A_BYTES;
        #pragma unroll
        for (int it = 0; it < 4; it++) {
            int id  = it * 256 + tid;
            int ar = id >> 3, akq = id & 7;
            int grow = m0 + ar; if (grow > M - 1) grow = M - 1;
            cp_async16(baseA + (uint32_t)(ar * APAD + akq * 4) * 4,
                       X + (size_t)grow * CIN + s * CTA_K + akq * 4);
            int bk = id >> 5, bnc = id & 31;
            cp_async16(baseB + (uint32_t)(bk * BPAD + bnc * 4) * 4,
                       g_W1R + (size_t)(s * CTA_K + bk) * CH + n0 + bnc * 4);
        }
    };

    issue(0, 0);
    CP_COMMIT();

    for (int s = 0; s < NSTG; s++) {
        int buf = s & 1;
        if (s + 1 < NSTG) {
            issue(s + 1, buf ^ 1);
            CP_COMMIT();
            CP_WAIT(1);
        } else {
            CP_WAIT(0);
        }
        __syncthreads();

        const float* sA = sm + buf * (SM_STAGE / 4);
        const float* sB = sA + (SM_A_BYTES / 4);

        #pragma unroll
        for (int ks = 0; ks < 4; ks++) {
            float a[2][4];
            #pragma unroll
            for (int mt = 0; mt < 2; mt++) {
                int r = wm * 32 + mt * 16 + gid;
                int c = ks * 8 + tig;
                a[mt][0] = to_tf32(sA[r * APAD + c]);
                a[mt][1] = to_tf32(sA[(r + 8) * APAD + c]);
                a[mt][2] = to_tf32(sA[r * APAD + c + 4]);
                a[mt][3] = to_tf32(sA[(r + 8) * APAD + c + 4]);
            }
            float b[8][2];
            #pragma unroll
            for (int nt = 0; nt < 8; nt++) {
                int kk = ks * 8 + tig;
                int cc = wn * 64 + nt * 8 + gid;
                b[nt][0] = sB[kk * BPAD + cc];
                b[nt][1] = sB[(kk + 4) * BPAD + cc];
            }
            #pragma unroll
            for (int mt = 0; mt < 2; mt++)
                #pragma unroll
                for (int nt = 0; nt < 8; nt++)
                    mma_tf32(acc[mt][nt], a[mt], b[nt]);
        }
        __syncthreads();
    }

    #pragma unroll
    for (int mt = 0; mt < 2; mt++) {
        int r0 = m0 + wm * 32 + mt * 16 + gid;
        #pragma unroll
        for (int nt = 0; nt < 8; nt++) {
            int c = n0 + wn * 64 + nt * 8 + 2 * tig;
            if (r0 < M)
                *(float2*)(g_H + (size_t)r0 * CH + c) =
                    make_float2(acc[mt][nt][0], acc[mt][nt][1]);
            if (r0 + 8 < M)
                *(float2*)(g_H + (size_t)(r0 + 8) * CH + c) =
                    make_float2(acc[mt][nt][2], acc[mt][nt][3]);
        }
    }
}

// ---------------------------------------------------------------------------
// threefry2x32, key = (0, 42), partitionable mode: bits = o0 ^ o1
// ---------------------------------------------------------------------------
__device__ __forceinline__ void threefry2x32(unsigned c0, unsigned c1,
                                             unsigned& o0, unsigned& o1) {
    const unsigned ks0 = 0u, ks1 = 42u;
    const unsigned ks2 = 0x1BD11BDAu ^ ks0 ^ ks1;
    unsigned x0 = c0 + ks0;
    unsigned x1 = c1 + ks1;
#define TF_ROUND(r) { x0 += x1; x1 = (x1 << (r)) | (x1 >> (32 - (r))); x1 ^= x0; }
    TF_ROUND(13) TF_ROUND(15) TF_ROUND(26) TF_ROUND(6)
    x0 += ks1; x1 += ks2 + 1u;
    TF_ROUND(17) TF_ROUND(29) TF_ROUND(16) TF_ROUND(24)
    x0 += ks2; x1 += ks0 + 2u;
    TF_ROUND(13) TF_ROUND(15) TF_ROUND(26) TF_ROUND(6)
    x0 += ks0; x1 += ks1 + 3u;
    TF_ROUND(17) TF_ROUND(29) TF_ROUND(16) TF_ROUND(24)
    x0 += ks1; x1 += ks2 + 4u;
    TF_ROUND(13) TF_ROUND(15) TF_ROUND(26) TF_ROUND(6)
    x0 += ks2; x1 += ks0 + 5u;
#undef TF_ROUND
    o0 = x0; o1 = x1;
}

__device__ __forceinline__ float dropout_elu(float acc, float bias, unsigned idx) {
    unsigned o0, o1;
    threefry2x32(0u, idx, o0, o1);
    unsigned bits = o0 ^ o1;
    float u = __uint_as_float((bits >> 9) | 0x3F800000u) - 1.0f;
    float val = acc + bias;
    val = val > 0.0f ? val : expm1f(val);
    return (u < 0.75f) ? val * (1.0f / 0.75f) : 0.0f;
}

// ---------------------------------------------------------------------------
// Layer-1 aggregate + epilogue + fused GEMM2 (exact R8 version).
// ---------------------------------------------------------------------------
__global__ __launch_bounds__(256) void gather1_kernel(
    const float* __restrict__ b1, const float* __restrict__ W2, int M)
{
    int grp = threadIdx.x >> 6;
    int t   = threadIdx.x & 63;
    int v   = blockIdx.x * 4 + grp;
    bool active = (v < M);
    int vv = active ? v : 0;

    const float4* __restrict__ H4 = (const float4*)g_H;

    float dv = g_DINV[vv];
    float4 h = H4[(size_t)vv * 64 + t];
    float s2 = dv * dv;
    float4 acc = make_float4(s2 * h.x, s2 * h.y, s2 * h.z, s2 * h.w);

    int beg = active ? g_ROWPTR[vv]     : 0;
    int end = active ? g_ROWPTR[vv + 1] : 0;

    int j = beg;
    for (; j + 4 <= end; j += 4) {
        int   s0 = g_SRC[j],      s1 = g_SRC[j + 1];
        int   s2i = g_SRC[j + 2], s3 = g_SRC[j + 3];
        float n0 = g_NRM[j],      n1 = g_NRM[j + 1];
        float n2 = g_NRM[j + 2],  n3 = g_NRM[j + 3];
        float4 r0 = H4[(size_t)s0 * 64 + t];
        float4 r1 = H4[(size_t)s1 * 64 + t];
        float4 r2 = H4[(size_t)s2i * 64 + t];
        float4 r3 = H4[(size_t)s3 * 64 + t];
        acc.x += n0 * r0.x + n1 * r1.x + n2 * r2.x + n3 * r3.x;
        acc.y += n0 * r0.y + n1 * r1.y + n2 * r2.y + n3 * r3.y;
        acc.z += n0 * r0.z + n1 * r1.z + n2 * r2.z + n3 * r3.z;
        acc.w += n0 * r0.w + n1 * r1.w + n2 * r2.w + n3 * r3.w;
    }
    for (; j < end; j++) {
        int   s0 = g_SRC[j];
        float n0 = g_NRM[j];
        float4 r0 = H4[(size_t)s0 * 64 + t];
        acc.x += n0 * r0.x;
        acc.y += n0 * r0.y;
        acc.z += n0 * r0.z;
        acc.w += n0 * r0.w;
    }

    float4 bb = ((const float4*)b1)[t];
    unsigned base = (unsigned)vv * CH + (unsigned)t * 4;
    float a0 = dropout_elu(acc.x, bb.x, base + 0);
    float a1 = dropout_elu(acc.y, bb.y, base + 1);
    float a2 = dropout_elu(acc.z, bb.z, base + 2);
    float a3 = dropout_elu(acc.w, bb.w, base + 3);

    float4 w = ((const float4*)W2)[t];
    float dot = a0 * w.x + a1 * w.y + a2 * w.z + a3 * w.w;
    #pragma unroll
    for (int o = 16; o > 0; o >>= 1)
        dot += __shfl_xor_sync(0xffffffffu, dot, o);

    __shared__ float red[8];
    int lane = t & 31, hw = t >> 5;
    if (lane == 0) red[grp * 2 + hw] = dot;
    __syncthreads();
    if (t == 0 && active) g_P[v] = red[grp * 2] + red[grp * 2 + 1];
}

// ---------------------------------------------------------------------------
// Layer-2 aggregate (CSR gather, scalar). One warp per node.
// ---------------------------------------------------------------------------
__global__ void gather2_kernel(const float* __restrict__ b2,
                               float* __restrict__ out, int M) {
    int gt   = blockIdx.x * blockDim.x + threadIdx.x;
    int warp = gt >> 5;
    int lane = gt & 31;
    if (warp >= M) return;
    int beg = g_ROWPTR[warp];
    int end = g_ROWPTR[warp + 1];
    float s = 0.0f;
    for (int e = beg + lane; e < end; e += 32)
        s += g_NRM[e] * g_P[g_SRC[e]];
    #pragma unroll
    for (int o = 16; o > 0; o >>= 1) s += __shfl_xor_sync(0xffffffffu, s, o);
    if (lane == 0) {
        float dv = g_DINV[warp];
        out[warp] = dv * dv * g_P[warp] + b2[0] + s;
    }
}

// ---------------------------------------------------------------------------
extern "C" void kernel_launch(void* const* d_in, const int* in_sizes, int n_in,
                              void* d_out, int out_size) {
    const float* x  = (const float*)d_in[0];
    const void*  ei = d_in[1];
    const float* W1 = (const float*)d_in[2];
    const float* b1 = (const float*)d_in[3];
    const float* W2 = (const float*)d_in[4];
    const float* b2 = (const float*)d_in[5];
    float* out = (float*)d_out;

    int M = in_sizes[0] / CIN;     // 50000
    int E = in_sizes[1] / 2;       // 800000
    int nb = (M + 255) / 256;      // 196

    static cudaStream_t s2 = nullptr;
    static cudaEvent_t evFork = nullptr, evJoin = nullptr;
    if (!s2) {
        cudaFuncSetAttribute(gemm1_mma_kernel,
                             cudaFuncAttributeMaxDynamicSharedMemorySize, SM_TOTAL);
        cudaStreamCreateWithFlags(&s2, cudaStreamNonBlocking);
        cudaEventCreateWithFlags(&evFork, cudaEventDisableTiming);
        cudaEventCreateWithFlags(&evJoin, cudaEventDisableTiming);
    }

    // ---- fork: CSR build on s2, GEMM1 on stream 0 ----
    cudaEventRecord(evFork, 0);
    cudaStreamWaitEvent(s2, evFork, 0);

    detect_kernel  <<<1, 32, 0, s2>>>((const unsigned*)ei, E);
    deg_zero_kernel<<<nb, 256, 0, s2>>>(M);
    deg_acc_kernel <<<(E + 255) / 256, 256, 0, s2>>>(ei, E);
    dinv_kernel    <<<nb, 256, 0, s2>>>(M);
    scan1_kernel   <<<nb, 256, 0, s2>>>(M);
    scan2_kernel   <<<1, 256, 0, s2>>>(nb);
    scan3_kernel   <<<nb, 256, 0, s2>>>(M);
    fill_kernel    <<<(E + 255) / 256, 256, 0, s2>>>(ei, E);

    w1r_kernel<<<(CIN * CH + 255) / 256, 256>>>(W1);
    dim3 g1((M + CTA_M - 1) / CTA_M, CH / CTA_N);  // (391, 2)
    gemm1_mma_kernel<<<g1, 256, SM_TOTAL>>>(x, M);

    cudaEventRecord(evJoin, s2);
    cudaStreamWaitEvent(0, evJoin, 0);

    gather1_kernel<<<(M + 3) / 4, 256>>>(b1, W2, M);
    gather2_kernel<<<(M * 32 + 255) / 256, 256>>>(b2, out, M);
}

// round 12
// speedup vs baseline: 1.7223x; 1.0249x over previous
#include <cuda_runtime.h>
#include <cstdint>

// ---------------------------------------------------------------------------
// GCN 2-layer forward on GB300 — round 12: GEMM1 widened to CTA 128x256
// (X read once, better mma/LDS ratio); submissions reordered so ncu's
// skip-5/capture-1 lands on gemm1 next round.
//   h  = x @ W1                 (mma.sync tf32, 50000x512 @ 512x256)
//   a1 = Dinv (A+I) Dinv h ; +b1 ; ELU ; dropout(p=0.25, jax threefry)
//   p  = a1 @ W2                (fused: group dot-product in gather1)
//   out= Dinv (A+I) Dinv p + b2
// ---------------------------------------------------------------------------

#define NMAX 50048
#define EMAX 1000000
#define CIN  512
#define CH   256
#define SCAN_NB ((NMAX + 255) / 256)   // 196 tiles

// GEMM1 tiling: CTA 128x256x32
#define CTA_M 128
#define CTA_N 256
#define CTA_K 32
#define NSTG  (CIN / CTA_K)          // 16
#define APAD  36
#define BPAD  264
#define SM_A_BYTES (CTA_M * APAD * 4)            // 18432
#define SM_B_BYTES (CTA_K * BPAD * 4)            // 33792
#define SM_STAGE   (SM_A_BYTES + SM_B_BYTES)     // 52224
#define SM_TOTAL   (2 * SM_STAGE)                // 104448

__device__ int    g_DEGI[NMAX];
__device__ float  g_DINV[NMAX];
__device__ int    g_ROWPTR[NMAX + 1];
__device__ int    g_CUR[NMAX];
__device__ int    g_PART[SCAN_NB];
__device__ int    g_SRC[EMAX];
__device__ float  g_NRM[EMAX];
__device__ float  g_H  [(size_t)NMAX * CH];
__device__ float  g_P  [NMAX];
__device__ float  g_W1R[(size_t)CIN * CH];
__device__ int    g_is64;

__device__ __forceinline__ float to_tf32(float x) {
    float r;
    asm("cvt.rna.tf32.f32 %0, %1;" : "=f"(r) : "f"(x));
    return r;
}
__device__ __forceinline__ uint32_t smem_u32(const void* p) {
    uint32_t a;
    asm("{ .reg .u64 t; cvta.to.shared.u64 t, %1; cvt.u32.u64 %0, t; }"
        : "=r"(a) : "l"(p));
    return a;
}
__device__ __forceinline__ void cp_async16(uint32_t dst, const void* src) {
    asm volatile("cp.async.ca.shared.global [%0], [%1], 16;"
                 :: "r"(dst), "l"(src));
}
#define CP_COMMIT() asm volatile("cp.async.commit_group;" ::: "memory")
#define CP_WAIT(n)  asm volatile("cp.async.wait_group %0;" :: "n"(n) : "memory")

__device__ __forceinline__ void mma_tf32(float* c, const float* a, const float* b) {
    asm volatile(
        "mma.sync.aligned.m16n8k8.row.col.f32.tf32.tf32.f32 "
        "{%0,%1,%2,%3}, {%4,%5,%6,%7}, {%8,%9}, {%0,%1,%2,%3};"
        : "+f"(c[0]), "+f"(c[1]), "+f"(c[2]), "+f"(c[3])
        : "r"(__float_as_uint(a[0])), "r"(__float_as_uint(a[1])),
          "r"(__float_as_uint(a[2])), "r"(__float_as_uint(a[3])),
          "r"(__float_as_uint(b[0])), "r"(__float_as_uint(b[1])));
}

// ---------------------------------------------------------------------------
__global__ void detect_kernel(const unsigned* __restrict__ words, int E) {
    if (threadIdx.x == 0 && blockIdx.x == 0) {
        int n = E < 256 ? E : 256;
        unsigned acc = 0u;
        for (int i = 0; i < n; i++) acc |= words[2 * i + 1];
        g_is64 = (acc == 0u) ? 1 : 0;
    }
}
__device__ __forceinline__ int edge_at(const void* ei, int is64, long long idx) {
    if (is64) return (int)((const long long*)ei)[idx];
    return ((const int*)ei)[idx];
}

// ---------------------------------------------------------------------------
__global__ void deg_zero_kernel(int M) {
    int v = blockIdx.x * blockDim.x + threadIdx.x;
    if (v < M) g_DEGI[v] = 0;
}
__global__ void deg_acc_kernel(const void* __restrict__ ei, int E) {
    int e = blockIdx.x * blockDim.x + threadIdx.x;
    if (e >= E) return;
    int d = edge_at(ei, g_is64, (long long)E + e);
    atomicAdd(&g_DEGI[d], 1);
}
__global__ void dinv_kernel(int M) {
    int v = blockIdx.x * blockDim.x + threadIdx.x;
    if (v < M) g_DINV[v] = rsqrtf((float)(g_DEGI[v] + 1));
}

// ---------------------------------------------------------------------------
// 3-phase parallel exclusive scan of DEGI -> ROWPTR, CUR
// ---------------------------------------------------------------------------
__device__ __forceinline__ int block_incl_scan(int val, int* smem32) {
    int lane = threadIdx.x & 31, wid = threadIdx.x >> 5;
    int v = val;
    #pragma unroll
    for (int o = 1; o < 32; o <<= 1) {
        int t = __shfl_up_sync(0xffffffffu, v, o);
        if (lane >= o) v += t;
    }
    if (lane == 31) smem32[wid] = v;
    __syncthreads();
    if (wid == 0) {
        int w = (lane < 8) ? smem32[lane] : 0;
        #pragma unroll
        for (int o = 1; o < 8; o <<= 1) {
            int t = __shfl_up_sync(0xffffffffu, w, o);
            if (lane >= o) w += t;
        }
        if (lane < 8) smem32[lane] = w;
    }
    __syncthreads();
    return v + (wid > 0 ? smem32[wid - 1] : 0);
}

__global__ __launch_bounds__(256) void scan1_kernel(int M) {
    __shared__ int sm32[32];
    int i = blockIdx.x * 256 + threadIdx.x;
    int d = (i < M) ? g_DEGI[i] : 0;
    int incl = block_incl_scan(d, sm32);
    if (threadIdx.x == 255) g_PART[blockIdx.x] = incl;
}

__global__ __launch_bounds__(256) void scan2_kernel(int nb) {
    __shared__ int sm32[32];
    int tid = threadIdx.x;
    int v = (tid < nb) ? g_PART[tid] : 0;
    int incl = block_incl_scan(v, sm32);
    if (tid < nb) g_PART[tid] = incl - v;   // exclusive
}

__global__ __launch_bounds__(256) void scan3_kernel(int M) {
    __shared__ int sm32[32];
    int i = blockIdx.x * 256 + threadIdx.x;
    int d = (i < M) ? g_DEGI[i] : 0;
    int incl = block_incl_scan(d, sm32);
    int off = g_PART[blockIdx.x] + incl - d;
    if (i < M) {
        g_ROWPTR[i] = off;
        g_CUR[i]    = off;
        if (i == M - 1) g_ROWPTR[M] = off + d;
    }
}

__global__ void fill_kernel(const void* __restrict__ ei, int E) {
    int e = blockIdx.x * blockDim.x + threadIdx.x;
    if (e >= E) return;
    int is64 = g_is64;
    int s = edge_at(ei, is64, e);
    int d = edge_at(ei, is64, (long long)E + e);
    int pos = atomicAdd(&g_CUR[d], 1);
    g_SRC[pos] = s;
    g_NRM[pos] = g_DINV[s] * g_DINV[d];
}

// ---------------------------------------------------------------------------
__global__ void w1r_kernel(const float* __restrict__ W1) {
    int idx = blockIdx.x * blockDim.x + threadIdx.x;
    if (idx < CIN * CH) g_W1R[idx] = to_tf32(W1[idx]);
}

// ---------------------------------------------------------------------------
// GEMM1: g_H = X @ W1 via mma.sync.m16n8k8 tf32.
// CTA 128x256, 8 warps (4m x 2n), warp tile 32x128. cp.async double buffer.
// ---------------------------------------------------------------------------
__global__ __launch_bounds__(256, 1) void gemm1_mma_kernel(
    const float* __restrict__ X, int M)
{
    extern __shared__ float sm[];
    uint32_t smb = smem_u32(sm);

    int tid  = threadIdx.x;
    int wid  = tid >> 5;
    int lane = tid & 31;
    int gid  = lane >> 2;      // 0..7
    int tig  = lane & 3;       // 0..3
    int wm   = wid >> 1;       // 0..3
    int wn   = wid & 1;        // 0..1

    int m0 = blockIdx.x * CTA_M;
    const int n0 = 0;

    float acc[2][16][4];
    #pragma unroll
    for (int i = 0; i < 2; i++)
        #pragma unroll
        for (int j = 0; j < 16; j++)
            #pragma unroll
            for (int k = 0; k < 4; k++) acc[i][j][k] = 0.0f;

    auto issue = [&](int s, int buf) {
        uint32_t baseA = smb + buf * SM_STAGE;
        uint32_t baseB = baseA + SM_A_BYTES;
        // A tile: 128x32 floats = 1024 float4, 4 iters
        #pragma unroll
        for (int it = 0; it < 4; it++) {
            int id  = it * 256 + tid;
            int ar = id >> 3, akq = id & 7;
            int grow = m0 + ar; if (grow > M - 1) grow = M - 1;
            cp_async16(baseA + (uint32_t)(ar * APAD + akq * 4) * 4,
                       X + (size_t)grow * CIN + s * CTA_K + akq * 4);
        }
        // B tile: 32x256 floats = 2048 float4, 8 iters
        #pragma unroll
        for (int it = 0; it < 8; it++) {
            int id  = it * 256 + tid;
            int bk = id >> 6, bnc = id & 63;
            cp_async16(baseB + (uint32_t)(bk * BPAD + bnc * 4) * 4,
                       g_W1R + (size_t)(s * CTA_K + bk) * CH + n0 + bnc * 4);
        }
    };

    issue(0, 0);
    CP_COMMIT();

    for (int s = 0; s < NSTG; s++) {
        int buf = s & 1;
        if (s + 1 < NSTG) {
            issue(s + 1, buf ^ 1);
            CP_COMMIT();
            CP_WAIT(1);
        } else {
            CP_WAIT(0);
        }
        __syncthreads();

        const float* sA = sm + buf * (SM_STAGE / 4);
        const float* sB = sA + (SM_A_BYTES / 4);

        #pragma unroll
        for (int ks = 0; ks < 4; ks++) {
            float a[2][4];
            #pragma unroll
            for (int mt = 0; mt < 2; mt++) {
                int r = wm * 32 + mt * 16 + gid;
                int c = ks * 8 + tig;
                a[mt][0] = to_tf32(sA[r * APAD + c]);
                a[mt][1] = to_tf32(sA[(r + 8) * APAD + c]);
                a[mt][2] = to_tf32(sA[r * APAD + c + 4]);
                a[mt][3] = to_tf32(sA[(r + 8) * APAD + c + 4]);
            }
            float b[16][2];
            #pragma unroll
            for (int nt = 0; nt < 16; nt++) {
                int kk = ks * 8 + tig;
                int cc = wn * 128 + nt * 8 + gid;
                b[nt][0] = sB[kk * BPAD + cc];
                b[nt][1] = sB[(kk + 4) * BPAD + cc];
            }
            #pragma unroll
            for (int mt = 0; mt < 2; mt++)
                #pragma unroll
                for (int nt = 0; nt < 16; nt++)
                    mma_tf32(acc[mt][nt], a[mt], b[nt]);
        }
        __syncthreads();
    }

    #pragma unroll
    for (int mt = 0; mt < 2; mt++) {
        int r0 = m0 + wm * 32 + mt * 16 + gid;
        #pragma unroll
        for (int nt = 0; nt < 16; nt++) {
            int c = n0 + wn * 128 + nt * 8 + 2 * tig;
            if (r0 < M)
                *(float2*)(g_H + (size_t)r0 * CH + c) =
                    make_float2(acc[mt][nt][0], acc[mt][nt][1]);
            if (r0 + 8 < M)
                *(float2*)(g_H + (size_t)(r0 + 8) * CH + c) =
                    make_float2(acc[mt][nt][2], acc[mt][nt][3]);
        }
    }
}

// ---------------------------------------------------------------------------
// threefry2x32, key = (0, 42), partitionable mode: bits = o0 ^ o1
// ---------------------------------------------------------------------------
__device__ __forceinline__ void threefry2x32(unsigned c0, unsigned c1,
                                             unsigned& o0, unsigned& o1) {
    const unsigned ks0 = 0u, ks1 = 42u;
    const unsigned ks2 = 0x1BD11BDAu ^ ks0 ^ ks1;
    unsigned x0 = c0 + ks0;
    unsigned x1 = c1 + ks1;
#define TF_ROUND(r) { x0 += x1; x1 = (x1 << (r)) | (x1 >> (32 - (r))); x1 ^= x0; }
    TF_ROUND(13) TF_ROUND(15) TF_ROUND(26) TF_ROUND(6)
    x0 += ks1; x1 += ks2 + 1u;
    TF_ROUND(17) TF_ROUND(29) TF_ROUND(16) TF_ROUND(24)
    x0 += ks2; x1 += ks0 + 2u;
    TF_ROUND(13) TF_ROUND(15) TF_ROUND(26) TF_ROUND(6)
    x0 += ks0; x1 += ks1 + 3u;
    TF_ROUND(17) TF_ROUND(29) TF_ROUND(16) TF_ROUND(24)
    x0 += ks1; x1 += ks2 + 4u;
    TF_ROUND(13) TF_ROUND(15) TF_ROUND(26) TF_ROUND(6)
    x0 += ks2; x1 += ks0 + 5u;
#undef TF_ROUND
    o0 = x0; o1 = x1;
}

__device__ __forceinline__ float dropout_elu(float acc, float bias, unsigned idx) {
    unsigned o0, o1;
    threefry2x32(0u, idx, o0, o1);
    unsigned bits = o0 ^ o1;
    float u = __uint_as_float((bits >> 9) | 0x3F800000u) - 1.0f;
    float val = acc + bias;
    val = val > 0.0f ? val : expm1f(val);
    return (u < 0.75f) ? val * (1.0f / 0.75f) : 0.0f;
}

// ---------------------------------------------------------------------------
// Layer-1 aggregate + epilogue + fused GEMM2 (unchanged from R8/R11).
// ---------------------------------------------------------------------------
__global__ __launch_bounds__(256) void gather1_kernel(
    const float* __restrict__ b1, const float* __restrict__ W2, int M)
{
    int grp = threadIdx.x >> 6;
    int t   = threadIdx.x & 63;
    int v   = blockIdx.x * 4 + grp;
    bool active = (v < M);
    int vv = active ? v : 0;

    const float4* __restrict__ H4 = (const float4*)g_H;

    float dv = g_DINV[vv];
    float4 h = H4[(size_t)vv * 64 + t];
    float s2 = dv * dv;
    float4 acc = make_float4(s2 * h.x, s2 * h.y, s2 * h.z, s2 * h.w);

    int beg = active ? g_ROWPTR[vv]     : 0;
    int end = active ? g_ROWPTR[vv + 1] : 0;

    int j = beg;
    for (; j + 4 <= end; j += 4) {
        int   s0 = g_SRC[j],      s1 = g_SRC[j + 1];
        int   s2i = g_SRC[j + 2], s3 = g_SRC[j + 3];
        float n0 = g_NRM[j],      n1 = g_NRM[j + 1];
        float n2 = g_NRM[j + 2],  n3 = g_NRM[j + 3];
        float4 r0 = H4[(size_t)s0 * 64 + t];
        float4 r1 = H4[(size_t)s1 * 64 + t];
        float4 r2 = H4[(size_t)s2i * 64 + t];
        float4 r3 = H4[(size_t)s3 * 64 + t];
        acc.x += n0 * r0.x + n1 * r1.x + n2 * r2.x + n3 * r3.x;
        acc.y += n0 * r0.y + n1 * r1.y + n2 * r2.y + n3 * r3.y;
        acc.z += n0 * r0.z + n1 * r1.z + n2 * r2.z + n3 * r3.z;
        acc.w += n0 * r0.w + n1 * r1.w + n2 * r2.w + n3 * r3.w;
    }
    for (; j < end; j++) {
        int   s0 = g_SRC[j];
        float n0 = g_NRM[j];
        float4 r0 = H4[(size_t)s0 * 64 + t];
        acc.x += n0 * r0.x;
        acc.y += n0 * r0.y;
        acc.z += n0 * r0.z;
        acc.w += n0 * r0.w;
    }

    float4 bb = ((const float4*)b1)[t];
    unsigned base = (unsigned)vv * CH + (unsigned)t * 4;
    float a0 = dropout_elu(acc.x, bb.x, base + 0);
    float a1 = dropout_elu(acc.y, bb.y, base + 1);
    float a2 = dropout_elu(acc.z, bb.z, base + 2);
    float a3 = dropout_elu(acc.w, bb.w, base + 3);

    float4 w = ((const float4*)W2)[t];
    float dot = a0 * w.x + a1 * w.y + a2 * w.z + a3 * w.w;
    #pragma unroll
    for (int o = 16; o > 0; o >>= 1)
        dot += __shfl_xor_sync(0xffffffffu, dot, o);

    __shared__ float red[8];
    int lane = t & 31, hw = t >> 5;
    if (lane == 0) red[grp * 2 + hw] = dot;
    __syncthreads();
    if (t == 0 && active) g_P[v] = red[grp * 2] + red[grp * 2 + 1];
}

// ---------------------------------------------------------------------------
// Layer-2 aggregate (CSR gather, scalar). One warp per node.
// ---------------------------------------------------------------------------
__global__ void gather2_kernel(const float* __restrict__ b2,
                               float* __restrict__ out, int M) {
    int gt   = blockIdx.x * blockDim.x + threadIdx.x;
    int warp = gt >> 5;
    int lane = gt & 31;
    if (warp >= M) return;
    int beg = g_ROWPTR[warp];
    int end = g_ROWPTR[warp + 1];
    float s = 0.0f;
    for (int e = beg + lane; e < end; e += 32)
        s += g_NRM[e] * g_P[g_SRC[e]];
    #pragma unroll
    for (int o = 16; o > 0; o >>= 1) s += __shfl_xor_sync(0xffffffffu, s, o);
    if (lane == 0) {
        float dv = g_DINV[warp];
        out[warp] = dv * dv * g_P[warp] + b2[0] + s;
    }
}

// ---------------------------------------------------------------------------
extern "C" void kernel_launch(void* const* d_in, const int* in_sizes, int n_in,
                              void* d_out, int out_size) {
    const float* x  = (const float*)d_in[0];
    const void*  ei = d_in[1];
    const float* W1 = (const float*)d_in[2];
    const float* b1 = (const float*)d_in[3];
    const float* W2 = (const float*)d_in[4];
    const float* b2 = (const float*)d_in[5];
    float* out = (float*)d_out;

    int M = in_sizes[0] / CIN;     // 50000
    int E = in_sizes[1] / 2;       // 800000
    int nb = (M + 255) / 256;      // 196

    static cudaStream_t s2 = nullptr;
    static cudaEvent_t evFork = nullptr, evJoin = nullptr;
    if (!s2) {
        cudaFuncSetAttribute(gemm1_mma_kernel,
                             cudaFuncAttributeMaxDynamicSharedMemorySize, SM_TOTAL);
        cudaStreamCreateWithFlags(&s2, cudaStreamNonBlocking);
        cudaEventCreateWithFlags(&evFork, cudaEventDisableTiming);
        cudaEventCreateWithFlags(&evJoin, cudaEventDisableTiming);
    }

    // ---- fork: CSR build on s2, GEMM1 on stream 0 ----
    // Submission order puts gemm1 at slot #4 so the ncu skip-window lands on it.
    cudaEventRecord(evFork, 0);
    cudaStreamWaitEvent(s2, evFork, 0);

    detect_kernel  <<<1, 32, 0, s2>>>((const unsigned*)ei, E);      // #1
    deg_zero_kernel<<<nb, 256, 0, s2>>>(M);                          // #2
    w1r_kernel<<<(CIN * CH + 255) / 256, 256>>>(W1);                 // #3 (s0)
    dim3 g1((M + CTA_M - 1) / CTA_M, 1);  // (391, 1)
    gemm1_mma_kernel<<<g1, 256, SM_TOTAL>>>(x, M);                   // #4 (s0)

    deg_acc_kernel <<<(E + 255) / 256, 256, 0, s2>>>(ei, E);         // #5
    dinv_kernel    <<<nb, 256, 0, s2>>>(M);                          // #6
    scan1_kernel   <<<nb, 256, 0, s2>>>(M);                          // #7
    scan2_kernel   <<<1, 256, 0, s2>>>(nb);                          // #8
    scan3_kernel   <<<nb, 256, 0, s2>>>(M);                          // #9
    fill_kernel    <<<(E + 255) / 256, 256, 0, s2>>>(ei, E);         // #10

    cudaEventRecord(evJoin, s2);
    cudaStreamWaitEvent(0, evJoin, 0);

    gather1_kernel<<<(M + 3) / 4, 256>>>(b1, W2, M);                 // #11
    gather2_kernel<<<(M * 32 + 255) / 256, 256>>>(b2, out, M);       // #12
}